// round 1
// baseline (speedup 1.0000x reference)
#include <cuda_runtime.h>
#include <math.h>
#include <stdint.h>

#define NN 50000
#define TT 8
#define HH 128
#define EE 800000

// ---------------- scratch (device globals; no allocation allowed) ----------
__device__ float g_h0[NN * HH];
__device__ float g_h1[NN * HH];
__device__ float g_hs[NN * HH];
__device__ float g_cur[NN * HH];
__device__ float g_cur2[NN * HH];
__device__ float g_u[NN * HH];
__device__ float g_r[NN * HH];
__device__ int   g_deg[NN];
__device__ int   g_rowptr[NN + 1];
__device__ int   g_cursor[NN];
__device__ int   g_csrc[EE];
__device__ float g_dinv[NN];

// ---------------- small utility kernels ------------------------------------
__global__ void zero_f_kernel(float* p, int n) {
    for (int i = blockIdx.x * blockDim.x + threadIdx.x; i < n; i += gridDim.x * blockDim.x)
        p[i] = 0.0f;
}

__global__ void zero_deg_kernel(int n) {
    for (int i = blockIdx.x * blockDim.x + threadIdx.x; i < n; i += gridDim.x * blockDim.x)
        g_deg[i] = 0;
}

__global__ void hist_kernel(const int* __restrict__ dst, int e) {
    for (int i = blockIdx.x * blockDim.x + threadIdx.x; i < e; i += gridDim.x * blockDim.x)
        atomicAdd(&g_deg[dst[i]], 1);
}

// single-block exclusive scan over g_deg -> g_rowptr / g_cursor, plus dinv
__global__ void scan_kernel(int n) {
    __shared__ int wsum[32];
    __shared__ int sbase;
    const int lane = threadIdx.x & 31;
    const int wid  = threadIdx.x >> 5;
    if (threadIdx.x == 0) sbase = 0;
    __syncthreads();
    for (int start = 0; start < n; start += 1024) {
        int i = start + (int)threadIdx.x;
        int v = (i < n) ? g_deg[i] : 0;
        int incl = v;
        #pragma unroll
        for (int off = 1; off < 32; off <<= 1) {
            int t = __shfl_up_sync(0xffffffffu, incl, off);
            if (lane >= off) incl += t;
        }
        if (lane == 31) wsum[wid] = incl;
        __syncthreads();
        if (wid == 0) {
            int w = wsum[lane];
            #pragma unroll
            for (int off = 1; off < 32; off <<= 1) {
                int t = __shfl_up_sync(0xffffffffu, w, off);
                if (lane >= off) w += t;
            }
            wsum[lane] = w;
        }
        __syncthreads();
        int excl = sbase + (incl - v) + (wid > 0 ? wsum[wid - 1] : 0);
        if (i < n) {
            g_rowptr[i] = excl;
            g_cursor[i] = excl;
            g_dinv[i]   = rsqrtf((float)v + 1.0f);
        }
        __syncthreads();
        if (threadIdx.x == 0) sbase += wsum[31];
        __syncthreads();
    }
    if (threadIdx.x == 0) g_rowptr[n] = sbase;
}

__global__ void fill_kernel(const int* __restrict__ src, const int* __restrict__ dst, int e) {
    for (int i = blockIdx.x * blockDim.x + threadIdx.x; i < e; i += gridDim.x * blockDim.x) {
        int slot = atomicAdd(&g_cursor[dst[i]], 1);
        g_csrc[slot] = src[i];
    }
}

// out[n,f] = act( dinv[n] * ( hs[n,f] + sum_{src in CSR(n)} hs[src,f] ) + bias[f] )
__global__ void gather_kernel(const float* __restrict__ hs,
                              const float* __restrict__ bias,
                              float* __restrict__ out, int relu) {
    const int node = blockIdx.x;
    const int f = threadIdx.x;
    const int beg = g_rowptr[node];
    const int end = g_rowptr[node + 1];
    float acc = hs[(size_t)node * HH + f];
    int j = beg;
    for (; j + 4 <= end; j += 4) {
        int s0 = g_csrc[j], s1 = g_csrc[j + 1], s2 = g_csrc[j + 2], s3 = g_csrc[j + 3];
        float a0 = hs[(size_t)s0 * HH + f];
        float a1 = hs[(size_t)s1 * HH + f];
        float a2 = hs[(size_t)s2 * HH + f];
        float a3 = hs[(size_t)s3 * HH + f];
        acc += (a0 + a1) + (a2 + a3);
    }
    for (; j < end; ++j) acc += hs[(size_t)g_csrc[j] * HH + f];
    float v = g_dinv[node] * acc + bias[f];
    if (relu) v = fmaxf(v, 0.0f);
    out[(size_t)node * HH + f] = v;
}

// ---------------- fused GEMM ------------------------------------------------
// C(n x 128) = [A1 | A2 (*A2mul)] (n x K) @ B (K x 128), fused epilogues.
#define EPI_SCALE 0   // out = acc * dinv[row]                       (pre-agg)
#define EPI_SIG   1   // out = sigmoid(acc + bias[col])              (u, r)
#define EPI_GRU   2   // out = hp + u*(tanh(acc+bias) - hp)          (state upd)
#define EPI_BIAS  3   // out = acc + bias[col]                       (output)

__global__ __launch_bounds__(256) void gemm_kernel(
    const float* __restrict__ A1, const float* __restrict__ A2,
    const float* __restrict__ A2mul, const float* __restrict__ B,
    const float* __restrict__ bias, const float* __restrict__ dinv,
    const float* __restrict__ u, const float* __restrict__ hprev,
    float* __restrict__ out, int n, int K, int epi)
{
    __shared__ float As[16][128];
    __shared__ float Bs[16][128];
    const int tid = threadIdx.x;
    const int tx = tid & 15;         // output col group
    const int ty = tid >> 4;         // output row group
    const int row0 = blockIdx.x * 128;

    float acc[8][8];
    #pragma unroll
    for (int i = 0; i < 8; i++)
        #pragma unroll
        for (int j = 0; j < 8; j++) acc[i][j] = 0.0f;

    for (int k0 = 0; k0 < K; k0 += 16) {
        const float* Asrc = A1;
        int kc = k0;
        bool domul = false;
        if (k0 >= 128) { Asrc = A2; kc = k0 - 128; domul = (A2mul != nullptr); }

        // load A tile (128 x 16), stored transposed
        #pragma unroll
        for (int it = 0; it < 2; it++) {
            int lin = tid + it * 256;
            int r = lin >> 2;
            int c4 = (lin & 3) * 4;
            int grow = row0 + r;
            float4 v = make_float4(0.f, 0.f, 0.f, 0.f);
            if (grow < n) {
                v = *(const float4*)(Asrc + (size_t)grow * 128 + kc + c4);
                if (domul) {
                    float4 m = *(const float4*)(A2mul + (size_t)grow * 128 + kc + c4);
                    v.x *= m.x; v.y *= m.y; v.z *= m.z; v.w *= m.w;
                }
            }
            As[c4 + 0][r] = v.x; As[c4 + 1][r] = v.y;
            As[c4 + 2][r] = v.z; As[c4 + 3][r] = v.w;
        }
        // load B tile (16 x 128)
        #pragma unroll
        for (int it = 0; it < 2; it++) {
            int lin = tid + it * 256;
            int r = lin >> 5;
            int c4 = (lin & 31) * 4;
            *(float4*)(&Bs[r][c4]) = *(const float4*)(B + (size_t)(k0 + r) * 128 + c4);
        }
        __syncthreads();

        #pragma unroll
        for (int kk = 0; kk < 16; kk++) {
            float a[8], b[8];
            #pragma unroll
            for (int i = 0; i < 8; i++) a[i] = As[kk][ty * 8 + i];
            #pragma unroll
            for (int j = 0; j < 8; j++) b[j] = Bs[kk][tx * 8 + j];
            #pragma unroll
            for (int i = 0; i < 8; i++)
                #pragma unroll
                for (int j = 0; j < 8; j++) acc[i][j] += a[i] * b[j];
        }
        __syncthreads();
    }

    // epilogue
    float bv[8];
    if (bias) {
        #pragma unroll
        for (int j = 0; j < 8; j++) bv[j] = bias[tx * 8 + j];
    }
    #pragma unroll
    for (int i = 0; i < 8; i++) {
        int grow = row0 + ty * 8 + i;
        if (grow >= n) break;
        size_t off = (size_t)grow * 128 + tx * 8;
        float res[8];
        if (epi == EPI_SCALE) {
            float dv = dinv[grow];
            #pragma unroll
            for (int j = 0; j < 8; j++) res[j] = acc[i][j] * dv;
        } else if (epi == EPI_SIG) {
            #pragma unroll
            for (int j = 0; j < 8; j++) res[j] = 1.0f / (1.0f + expf(-(acc[i][j] + bv[j])));
        } else if (epi == EPI_GRU) {
            #pragma unroll
            for (int j = 0; j < 8; j++) {
                float hp = hprev[off + j];
                float uu = u[off + j];
                res[j] = hp + uu * (tanhf(acc[i][j] + bv[j]) - hp);
            }
        } else {
            #pragma unroll
            for (int j = 0; j < 8; j++) res[j] = acc[i][j] + bv[j];
        }
        *(float4*)(out + off)     = make_float4(res[0], res[1], res[2], res[3]);
        *(float4*)(out + off + 4) = make_float4(res[4], res[5], res[6], res[7]);
    }
}

// ---------------- driver ----------------------------------------------------
extern "C" void kernel_launch(void* const* d_in, const int* in_sizes, int n_in,
                              void* d_out, int out_size) {
    const float* x_seq = (const float*)d_in[0];
    const int*   ei    = (const int*)d_in[1];
    const float* W_in0 = (const float*)d_in[2];
    const float* b_in0 = (const float*)d_in[3];
    const float* W_h0  = (const float*)d_in[4];
    const float* b_h0  = (const float*)d_in[5];
    const float* Wu0   = (const float*)d_in[6];
    const float* bu0   = (const float*)d_in[7];
    const float* Wr0   = (const float*)d_in[8];
    const float* br0   = (const float*)d_in[9];
    const float* Wc0   = (const float*)d_in[10];
    const float* bc0   = (const float*)d_in[11];
    const float* W_in1 = (const float*)d_in[12];
    const float* b_in1 = (const float*)d_in[13];
    const float* W_h1  = (const float*)d_in[14];
    const float* b_h1  = (const float*)d_in[15];
    const float* Wu1   = (const float*)d_in[16];
    const float* bu1   = (const float*)d_in[17];
    const float* Wr1   = (const float*)d_in[18];
    const float* br1   = (const float*)d_in[19];
    const float* Wc1   = (const float*)d_in[20];
    const float* bc1   = (const float*)d_in[21];
    const float* W_out = (const float*)d_in[22];
    const float* b_out = (const float*)d_in[23];
    float* out = (float*)d_out;

    float *p_h0, *p_h1, *p_hs, *p_cur, *p_cur2, *p_u, *p_r, *p_dinv;
    cudaGetSymbolAddress((void**)&p_h0,   g_h0);
    cudaGetSymbolAddress((void**)&p_h1,   g_h1);
    cudaGetSymbolAddress((void**)&p_hs,   g_hs);
    cudaGetSymbolAddress((void**)&p_cur,  g_cur);
    cudaGetSymbolAddress((void**)&p_cur2, g_cur2);
    cudaGetSymbolAddress((void**)&p_u,    g_u);
    cudaGetSymbolAddress((void**)&p_r,    g_r);
    cudaGetSymbolAddress((void**)&p_dinv, g_dinv);

    const int GB = (NN + 127) / 128;   // gemm row blocks
    const int EB = (EE + 255) / 256;   // edge blocks

    // zero recurrent state
    zero_f_kernel<<<512, 256>>>(p_h0, NN * HH);
    zero_f_kernel<<<512, 256>>>(p_h1, NN * HH);

    for (int t = 0; t < TT; t++) {
        const int* src = ei + (size_t)t * 2 * EE;
        const int* dst = src + EE;
        const float* xin = x_seq + (size_t)t * NN * HH;

        // CSR + dinv for this timestep
        zero_deg_kernel<<<128, 256>>>(NN);
        hist_kernel<<<EB, 256>>>(dst, EE);
        scan_kernel<<<1, 1024>>>(NN);
        fill_kernel<<<EB, 256>>>(src, dst, EE);

        // ---- layer 0 cell (input xin, state g_h0) ----
        gemm_kernel<<<GB, 256>>>(xin, nullptr, nullptr, W_in0, nullptr, p_dinv,
                                 nullptr, nullptr, p_hs, NN, 128, EPI_SCALE);
        gather_kernel<<<NN, 128>>>(p_hs, b_in0, p_cur, 1);
        gemm_kernel<<<GB, 256>>>(p_cur, nullptr, nullptr, W_h0, nullptr, p_dinv,
                                 nullptr, nullptr, p_hs, NN, 128, EPI_SCALE);
        gather_kernel<<<NN, 128>>>(p_hs, b_h0, p_cur2, 0);
        gemm_kernel<<<GB, 256>>>(p_cur2, p_h0, nullptr, Wu0, bu0, nullptr,
                                 nullptr, nullptr, p_u, NN, 256, EPI_SIG);
        gemm_kernel<<<GB, 256>>>(p_cur2, p_h0, nullptr, Wr0, br0, nullptr,
                                 nullptr, nullptr, p_r, NN, 256, EPI_SIG);
        gemm_kernel<<<GB, 256>>>(p_cur2, p_h0, p_r, Wc0, bc0, nullptr,
                                 p_u, p_h0, p_h0, NN, 256, EPI_GRU);

        // ---- layer 1 cell (input g_h0, state g_h1) ----
        gemm_kernel<<<GB, 256>>>(p_h0, nullptr, nullptr, W_in1, nullptr, p_dinv,
                                 nullptr, nullptr, p_hs, NN, 128, EPI_SCALE);
        gather_kernel<<<NN, 128>>>(p_hs, b_in1, p_cur, 1);
        gemm_kernel<<<GB, 256>>>(p_cur, nullptr, nullptr, W_h1, nullptr, p_dinv,
                                 nullptr, nullptr, p_hs, NN, 128, EPI_SCALE);
        gather_kernel<<<NN, 128>>>(p_hs, b_h1, p_cur2, 0);
        gemm_kernel<<<GB, 256>>>(p_cur2, p_h1, nullptr, Wu1, bu1, nullptr,
                                 nullptr, nullptr, p_u, NN, 256, EPI_SIG);
        gemm_kernel<<<GB, 256>>>(p_cur2, p_h1, nullptr, Wr1, br1, nullptr,
                                 nullptr, nullptr, p_r, NN, 256, EPI_SIG);
        gemm_kernel<<<GB, 256>>>(p_cur2, p_h1, p_r, Wc1, bc1, nullptr,
                                 p_u, p_h1, p_h1, NN, 256, EPI_GRU);

        // ---- output projection ----
        gemm_kernel<<<GB, 256>>>(p_h1, nullptr, nullptr, W_out, b_out, nullptr,
                                 nullptr, nullptr, out + (size_t)t * NN * HH,
                                 NN, 128, EPI_BIAS);
    }
}